// round 11
// baseline (speedup 1.0000x reference)
#include <cuda_runtime.h>
#include <cuda_fp16.h>
#include <cmath>
#include <cstdint>

// InstantNGP hash-grid encoder, round 11 = round 8 bodies + homogeneous-warp
// mapping. Block = 512 threads = 16 warps handles 32 points; warp w does
// level w for all 32 points (warp-uniform branch, all loads in flight).
// xyz and results staged through smem so global I/O stays coalesced.
//  * levels 0-5: cell-packed fp16 tables (2 x LDG.128 per query).
//  * levels 6-15: fp16x2 hash tables, 4-entry LDG.128 windows; ix%4==3
//    lanes add 4 x 4B gathers (avg 5 loads/level).

#define NGP_L 16
#define NGP_T (1u << 19)
#define NGP_MASK ((1u << 19) - 1u)
#define PRIME_Y 2654435761u
#define PRIME_Z 805459861u

#define N_CELL 6                    // levels 0-5 cell-packed
#define NHASH  (NGP_L - N_CELL)     // 10 hashed levels (6-15)

#define QSCALE   65536.0f
#define QSCALE_I (1.0f / 65536.0f)

// cell-packed l0-5: sum (r+1)^2*(r+2) = 876,868 entries, 16B each
#define QCAP 880000
__device__ uint4 g_q[QCAP];

// hashed fp16 tables l6-15: 10 * 2^19 * 4B viewed as quads
#define HCONV_ITEMS (NHASH * (int)(NGP_T / 4))
__device__ uint4 g_ht[NHASH * (NGP_T / 4)];

struct NgpParams {
    float cell[NGP_L];
    int   res[NGP_L];
    int   qoff[N_CELL];
    int   ccum[N_CELL + 1];
};

__device__ __forceinline__ float2 hsel(const uint4& q, unsigned i)
{
    const unsigned v = (i & 2u) ? ((i & 1u) ? q.w : q.z)
                                : ((i & 1u) ? q.y : q.x);
    return __half22float2(*reinterpret_cast<const __half2*>(&v));
}
__device__ __forceinline__ float2 h2f(unsigned v)
{
    return __half22float2(*reinterpret_cast<const __half2*>(&v));
}

// -------- fused precompute: hconv (l6-15) + qpack (l0-5) --------------------
__global__ __launch_bounds__(256)
void ngp_prep_kernel(const float* __restrict__ tables, NgpParams p, int ntot)
{
    const int id = blockIdx.x * blockDim.x + threadIdx.x;
    if (id >= ntot) return;

    if (id < HCONV_ITEMS) {
        const float4* __restrict__ src =
            reinterpret_cast<const float4*>(tables)
            + (size_t)N_CELL * (NGP_T / 2) + (size_t)id * 2;
        const float4 a = __ldg(src);
        const float4 b = __ldg(src + 1);
        const __half2 e0 = __floats2half2_rn(a.x * QSCALE, a.y * QSCALE);
        const __half2 e1 = __floats2half2_rn(a.z * QSCALE, a.w * QSCALE);
        const __half2 e2 = __floats2half2_rn(b.x * QSCALE, b.y * QSCALE);
        const __half2 e3 = __floats2half2_rn(b.z * QSCALE, b.w * QSCALE);
        uint4 q;
        q.x = *reinterpret_cast<const unsigned*>(&e0);
        q.y = *reinterpret_cast<const unsigned*>(&e1);
        q.z = *reinterpret_cast<const unsigned*>(&e2);
        q.w = *reinterpret_cast<const unsigned*>(&e3);
        g_ht[id] = q;
        return;
    }

    int rel = id - HCONV_ITEMS;
    int lvl = 0;
    #pragma unroll
    for (int l = 0; l < N_CELL; l++)
        if (rel >= p.ccum[l] && rel < p.ccum[l + 1]) lvl = l;
    rel -= p.ccum[lvl];

    const int res = p.res[lvl];
    const int D1  = res + 1;
    const int ix  = rel % D1;
    const int t   = rel / D1;
    const int iy  = t % D1;
    const int iz  = t / D1;

    const unsigned hy0 = (unsigned)iy * PRIME_Y;
    const unsigned hy1 = hy0 + PRIME_Y;
    const unsigned hz  = (unsigned)iz * PRIME_Z;
    const unsigned ux  = (unsigned)ix;

    const float2* __restrict__ tab =
        reinterpret_cast<const float2*>(tables) + (unsigned)lvl * NGP_T;

    const float2 a00 = __ldg(tab + ((ux        ^ hy0 ^ hz) & NGP_MASK));
    const float2 a10 = __ldg(tab + (((ux + 1u) ^ hy0 ^ hz) & NGP_MASK));
    const float2 a01 = __ldg(tab + ((ux        ^ hy1 ^ hz) & NGP_MASK));
    const float2 a11 = __ldg(tab + (((ux + 1u) ^ hy1 ^ hz) & NGP_MASK));

    const __half2 h00 = __floats2half2_rn(a00.x * QSCALE, a00.y * QSCALE);
    const __half2 h10 = __floats2half2_rn(a10.x * QSCALE, a10.y * QSCALE);
    const __half2 h01 = __floats2half2_rn(a01.x * QSCALE, a01.y * QSCALE);
    const __half2 h11 = __floats2half2_rn(a11.x * QSCALE, a11.y * QSCALE);

    uint4 q;
    q.x = *reinterpret_cast<const unsigned*>(&h00);
    q.y = *reinterpret_cast<const unsigned*>(&h10);
    q.z = *reinterpret_cast<const unsigned*>(&h01);
    q.w = *reinterpret_cast<const unsigned*>(&h11);
    g_q[p.qoff[lvl] + rel] = q;
}

// ---------------- main kernel: homogeneous warps, smem staging --------------
__global__ __launch_bounds__(512)
void InstantNGP_kernel(const float* __restrict__ xyz,
                       float* __restrict__ out,
                       NgpParams p, int npts)
{
    __shared__ float  sxyz[96];          // 32 points * 3 coords
    __shared__ float2 sres[32][NGP_L + 1];  // +1 pad: breaks 128B bank stride

    const int base = blockIdx.x * 32;    // first point of this block

    // stage xyz (coalesced 384B)
    if (threadIdx.x < 96) {
        const int i = base * 3 + threadIdx.x;
        sxyz[threadIdx.x] = (i < npts * 3) ? __ldg(xyz + i) : 0.5f;
    }
    __syncthreads();

    const int lvl  = threadIdx.x >> 5;   // warp id = level (uniform per warp)
    const int lane = threadIdx.x & 31;
    const int pt   = base + lane;
    const bool live = (pt < npts);

    // lane*3 is coprime stride -> conflict-free LDS
    const float x = sxyz[lane * 3 + 0];
    const float y = sxyz[lane * 3 + 1];
    const float z = sxyz[lane * 3 + 2];

    const float cell = p.cell[lvl];
    const float ux = __fdiv_rn(x, cell);
    const float uy = __fdiv_rn(y, cell);
    const float uz = __fdiv_rn(z, cell);

    const float fx = floorf(ux), fy = floorf(uy), fz = floorf(uz);
    const float dx = ux - fx,    dy = uy - fy,    dz = uz - fz;

    const unsigned ix = (unsigned)(int)fx;
    const unsigned iy = (unsigned)(int)fy;
    const unsigned iz = (unsigned)(int)fz;

    const float wx0 = 1.0f - dx, wx1 = dx;
    const float wy0 = 1.0f - dy, wy1 = dy;
    const float wz0 = 1.0f - dz, wz1 = dz;

    float c0, c1;

    if (lvl < N_CELL) {
        // ---- cell-packed: 2 x LDG.128 fetch all 8 corners ----
        const int D1 = p.res[lvl] + 1;
        const int zs = D1 * D1;
        const int bse = p.qoff[lvl] + ((int)iz * D1 + (int)iy) * D1 + (int)ix;
        const uint4 qa = __ldg(g_q + bse);        // z = iz
        const uint4 qb = __ldg(g_q + bse + zs);   // z = iz+1

        const float2 a00 = h2f(qa.x), a10 = h2f(qa.y);
        const float2 a01 = h2f(qa.z), a11 = h2f(qa.w);
        const float2 b00 = h2f(qb.x), b10 = h2f(qb.y);
        const float2 b01 = h2f(qb.z), b11 = h2f(qb.w);

        const float w00 = wx0 * wy0, w10 = wx1 * wy0;
        const float w01 = wx0 * wy1, w11 = wx1 * wy1;

        float s0 = w00 * a00.x;            float s1 = w00 * a00.y;
        s0 = fmaf(w10, a10.x, s0);         s1 = fmaf(w10, a10.y, s1);
        s0 = fmaf(w01, a01.x, s0);         s1 = fmaf(w01, a01.y, s1);
        s0 = fmaf(w11, a11.x, s0);         s1 = fmaf(w11, a11.y, s1);
        float t0 = w00 * b00.x;            float t1 = w00 * b00.y;
        t0 = fmaf(w10, b10.x, t0);         t1 = fmaf(w10, b10.y, t1);
        t0 = fmaf(w01, b01.x, t0);         t1 = fmaf(w01, b01.y, t1);
        t0 = fmaf(w11, b11.x, t0);         t1 = fmaf(w11, b11.y, t1);

        c0 = wz0 * s0 + wz1 * t0;
        c1 = wz0 * s1 + wz1 * t1;
    } else {
        // ---- hashed: 4 quad loads (+4B extras for ix%4==3 lanes) ----
        const int hl = lvl - N_CELL;
        const unsigned m0 = (iy * PRIME_Y)           ^ (iz * PRIME_Z);
        const unsigned m1 = (iy * PRIME_Y)           ^ (iz * PRIME_Z + PRIME_Z);
        const unsigned m2 = (iy * PRIME_Y + PRIME_Y) ^ (iz * PRIME_Z);
        const unsigned m3 = (iy * PRIME_Y + PRIME_Y) ^ (iz * PRIME_Z + PRIME_Z);
        const unsigned h0 = (ix ^ m0) & NGP_MASK;
        const unsigned h1 = (ix ^ m1) & NGP_MASK;
        const unsigned h2 = (ix ^ m2) & NGP_MASK;
        const unsigned h3 = (ix ^ m3) & NGP_MASK;

        const uint4* __restrict__ ht = g_ht + hl * (NGP_T / 4);
        const uint4 q0 = __ldg(ht + (h0 >> 2));
        const uint4 q1 = __ldg(ht + (h1 >> 2));
        const uint4 q2 = __ldg(ht + (h2 >> 2));
        const uint4 q3 = __ldg(ht + (h3 >> 2));

        const unsigned jx = ix + 1u;
        const bool extra = (ix & 3u) == 3u;
        float2 e4, e5, e6, e7;
        if (extra) {
            const unsigned* __restrict__ ht32 =
                reinterpret_cast<const unsigned*>(g_ht) + hl * NGP_T;
            const unsigned v4 = __ldg(ht32 + ((jx ^ m0) & NGP_MASK));
            const unsigned v5 = __ldg(ht32 + ((jx ^ m1) & NGP_MASK));
            const unsigned v6 = __ldg(ht32 + ((jx ^ m2) & NGP_MASK));
            const unsigned v7 = __ldg(ht32 + ((jx ^ m3) & NGP_MASK));
            e4 = h2f(v4); e5 = h2f(v5); e6 = h2f(v6); e7 = h2f(v7);
        } else {
            e4 = hsel(q0, (jx ^ m0) & 3u);
            e5 = hsel(q1, (jx ^ m1) & 3u);
            e6 = hsel(q2, (jx ^ m2) & 3u);
            e7 = hsel(q3, (jx ^ m3) & 3u);
        }
        const float2 e0 = hsel(q0, h0 & 3u);
        const float2 e1 = hsel(q1, h1 & 3u);
        const float2 e2 = hsel(q2, h2 & 3u);
        const float2 e3 = hsel(q3, h3 & 3u);

        const float w0 = wx0 * wy0 * wz0;
        const float w1 = wx0 * wy0 * wz1;
        const float w2 = wx0 * wy1 * wz0;
        const float w3 = wx0 * wy1 * wz1;
        const float w4 = wx1 * wy0 * wz0;
        const float w5 = wx1 * wy0 * wz1;
        const float w6 = wx1 * wy1 * wz0;
        const float w7 = wx1 * wy1 * wz1;

        c0 = w0 * e0.x;  c1 = w0 * e0.y;
        c0 = fmaf(w1, e1.x, c0);  c1 = fmaf(w1, e1.y, c1);
        c0 = fmaf(w2, e2.x, c0);  c1 = fmaf(w2, e2.y, c1);
        c0 = fmaf(w3, e3.x, c0);  c1 = fmaf(w3, e3.y, c1);
        c0 = fmaf(w4, e4.x, c0);  c1 = fmaf(w4, e4.y, c1);
        c0 = fmaf(w5, e5.x, c0);  c1 = fmaf(w5, e5.y, c1);
        c0 = fmaf(w6, e6.x, c0);  c1 = fmaf(w6, e6.y, c1);
        c0 = fmaf(w7, e7.x, c0);  c1 = fmaf(w7, e7.y, c1);
    }

    // stage results, then one coalesced 4KB block store
    sres[lane][lvl] = make_float2(c0 * QSCALE_I, c1 * QSCALE_I);
    __syncthreads();

    const int o  = threadIdx.x;          // 512 entries = 32 pts * 16 lvls
    const int op = o >> 4;               // point slot
    const int ol = o & 15;               // level slot
    if (base + op < npts)
        reinterpret_cast<float2*>(out)[(base + op) * NGP_L + ol] = sres[op][ol];
}

extern "C" void kernel_launch(void* const* d_in, const int* in_sizes, int n_in,
                              void* d_out, int out_size)
{
    const float* xyz    = (const float*)d_in[0];
    const float* tables = (const float*)d_in[1];
    float* out          = (float*)d_out;
    const int npts = in_sizes[0] / 3;

    // Reference resolution chain, replicated exactly in libm double.
    NgpParams p;
    const double B = std::exp((std::log(2048.0) - std::log(16.0)) / 15.0);
    for (int i = 0; i < NGP_L; i++) {
        double res_d = std::floor(16.0 * std::pow(B, (double)i));
        float resf   = (float)res_d;
        p.cell[i] = 1.0f / resf;
        p.res[i]  = (int)res_d;
    }
    int qoff = 0;
    p.ccum[0] = 0;
    for (int i = 0; i < N_CELL; i++) {
        p.qoff[i] = qoff;
        const int r = p.res[i];
        const int n = (r + 1) * (r + 1) * (r + 2);
        qoff += n;
        p.ccum[i + 1] = p.ccum[i] + n;
    }

    // 1) fused precompute
    {
        const int ntot = HCONV_ITEMS + p.ccum[N_CELL];
        ngp_prep_kernel<<<(ntot + 255) / 256, 256>>>(tables, p, ntot);
    }
    // 2) main encode: one block per 32 points
    {
        const int nblocks = (npts + 31) / 32;
        InstantNGP_kernel<<<nblocks, 512>>>(xyz, out, p, npts);
    }
}

// round 12
// speedup vs baseline: 1.1718x; 1.1718x over previous
#include <cuda_runtime.h>
#include <cuda_fp16.h>
#include <cmath>
#include <cstdint>

// InstantNGP hash-grid encoder, round 12 = round 8 with cell-packing extended
// to level 6 (N_CELL 6 -> 7). Everything else byte-identical to round 8.
//  * levels 0-6: cell-packed fp16 tables (2 x LDG.128 per query).
//  * levels 7-15: fp16x2 hash tables, 4-entry LDG.128 windows; ix%4==3
//    lanes add 4 x 4B gathers (avg 5 loads/level).

#define NGP_L 16
#define NGP_T (1u << 19)
#define NGP_MASK ((1u << 19) - 1u)
#define PRIME_Y 2654435761u
#define PRIME_Z 805459861u

#define N_CELL 7                    // levels 0-6 cell-packed
#define NHASH  (NGP_L - N_CELL)     // 9 hashed levels (7-15)

#define QSCALE   65536.0f
#define QSCALE_I (1.0f / 65536.0f)

// cell-packed l0-6: sum (r+1)^2*(r+2) = 2,294,340 entries, 16B each
#define QCAP 2300000
__device__ uint4 g_q[QCAP];

// hashed fp16 tables l7-15: 9 * 2^19 * 4B viewed as quads
#define HCONV_ITEMS (NHASH * (int)(NGP_T / 4))
__device__ uint4 g_ht[NHASH * (NGP_T / 4)];

struct NgpParams {
    float cell[NGP_L];
    int   res[NGP_L];
    int   qoff[N_CELL];
    int   ccum[N_CELL + 1];
};

__device__ __forceinline__ float2 hsel(const uint4& q, unsigned i)
{
    const unsigned v = (i & 2u) ? ((i & 1u) ? q.w : q.z)
                                : ((i & 1u) ? q.y : q.x);
    return __half22float2(*reinterpret_cast<const __half2*>(&v));
}
__device__ __forceinline__ float2 h2f(unsigned v)
{
    return __half22float2(*reinterpret_cast<const __half2*>(&v));
}

// -------- fused precompute: hconv (l7-15) + qpack (l0-6) --------------------
__global__ __launch_bounds__(256)
void ngp_prep_kernel(const float* __restrict__ tables, NgpParams p, int ntot)
{
    const int id = blockIdx.x * blockDim.x + threadIdx.x;
    if (id >= ntot) return;

    if (id < HCONV_ITEMS) {
        const float4* __restrict__ src =
            reinterpret_cast<const float4*>(tables)
            + (size_t)N_CELL * (NGP_T / 2) + (size_t)id * 2;
        const float4 a = __ldg(src);
        const float4 b = __ldg(src + 1);
        const __half2 e0 = __floats2half2_rn(a.x * QSCALE, a.y * QSCALE);
        const __half2 e1 = __floats2half2_rn(a.z * QSCALE, a.w * QSCALE);
        const __half2 e2 = __floats2half2_rn(b.x * QSCALE, b.y * QSCALE);
        const __half2 e3 = __floats2half2_rn(b.z * QSCALE, b.w * QSCALE);
        uint4 q;
        q.x = *reinterpret_cast<const unsigned*>(&e0);
        q.y = *reinterpret_cast<const unsigned*>(&e1);
        q.z = *reinterpret_cast<const unsigned*>(&e2);
        q.w = *reinterpret_cast<const unsigned*>(&e3);
        g_ht[id] = q;
        return;
    }

    int rel = id - HCONV_ITEMS;
    int lvl = 0;
    #pragma unroll
    for (int l = 0; l < N_CELL; l++)
        if (rel >= p.ccum[l] && rel < p.ccum[l + 1]) lvl = l;
    rel -= p.ccum[lvl];

    const int res = p.res[lvl];
    const int D1  = res + 1;
    const int ix  = rel % D1;
    const int t   = rel / D1;
    const int iy  = t % D1;
    const int iz  = t / D1;

    const unsigned hy0 = (unsigned)iy * PRIME_Y;
    const unsigned hy1 = hy0 + PRIME_Y;
    const unsigned hz  = (unsigned)iz * PRIME_Z;
    const unsigned ux  = (unsigned)ix;

    const float2* __restrict__ tab =
        reinterpret_cast<const float2*>(tables) + (unsigned)lvl * NGP_T;

    const float2 a00 = __ldg(tab + ((ux        ^ hy0 ^ hz) & NGP_MASK));
    const float2 a10 = __ldg(tab + (((ux + 1u) ^ hy0 ^ hz) & NGP_MASK));
    const float2 a01 = __ldg(tab + ((ux        ^ hy1 ^ hz) & NGP_MASK));
    const float2 a11 = __ldg(tab + (((ux + 1u) ^ hy1 ^ hz) & NGP_MASK));

    const __half2 h00 = __floats2half2_rn(a00.x * QSCALE, a00.y * QSCALE);
    const __half2 h10 = __floats2half2_rn(a10.x * QSCALE, a10.y * QSCALE);
    const __half2 h01 = __floats2half2_rn(a01.x * QSCALE, a01.y * QSCALE);
    const __half2 h11 = __floats2half2_rn(a11.x * QSCALE, a11.y * QSCALE);

    uint4 q;
    q.x = *reinterpret_cast<const unsigned*>(&h00);
    q.y = *reinterpret_cast<const unsigned*>(&h10);
    q.z = *reinterpret_cast<const unsigned*>(&h01);
    q.w = *reinterpret_cast<const unsigned*>(&h11);
    g_q[p.qoff[lvl] + rel] = q;
}

// ---------------- main kernel (round-8 structure, unchanged) ----------------
__global__ __launch_bounds__(256)
void InstantNGP_kernel(const float* __restrict__ xyz,
                       float* __restrict__ out,
                       NgpParams p, int npts)
{
    const int gid = blockIdx.x * blockDim.x + threadIdx.x;
    const int pt  = gid >> 4;
    const int lvl = gid & 15;
    if (pt >= npts) return;

    const float x = __ldg(xyz + pt * 3 + 0);
    const float y = __ldg(xyz + pt * 3 + 1);
    const float z = __ldg(xyz + pt * 3 + 2);

    const float cell = p.cell[lvl];
    const float ux = __fdiv_rn(x, cell);
    const float uy = __fdiv_rn(y, cell);
    const float uz = __fdiv_rn(z, cell);

    const float fx = floorf(ux), fy = floorf(uy), fz = floorf(uz);
    const float dx = ux - fx,    dy = uy - fy,    dz = uz - fz;

    const unsigned ix = (unsigned)(int)fx;
    const unsigned iy = (unsigned)(int)fy;
    const unsigned iz = (unsigned)(int)fz;

    const float wx0 = 1.0f - dx, wx1 = dx;
    const float wy0 = 1.0f - dy, wy1 = dy;
    const float wz0 = 1.0f - dz, wz1 = dz;

    float c0, c1;

    if (lvl < N_CELL) {
        // ---- cell-packed: 2 x LDG.128 fetch all 8 corners ----
        const int D1 = p.res[lvl] + 1;
        const int zs = D1 * D1;
        const int base = p.qoff[lvl] + ((int)iz * D1 + (int)iy) * D1 + (int)ix;
        const uint4 qa = __ldg(g_q + base);        // z = iz
        const uint4 qb = __ldg(g_q + base + zs);   // z = iz+1

        const float2 a00 = h2f(qa.x), a10 = h2f(qa.y);
        const float2 a01 = h2f(qa.z), a11 = h2f(qa.w);
        const float2 b00 = h2f(qb.x), b10 = h2f(qb.y);
        const float2 b01 = h2f(qb.z), b11 = h2f(qb.w);

        const float w00 = wx0 * wy0, w10 = wx1 * wy0;
        const float w01 = wx0 * wy1, w11 = wx1 * wy1;

        float s0 = w00 * a00.x;            float s1 = w00 * a00.y;
        s0 = fmaf(w10, a10.x, s0);         s1 = fmaf(w10, a10.y, s1);
        s0 = fmaf(w01, a01.x, s0);         s1 = fmaf(w01, a01.y, s1);
        s0 = fmaf(w11, a11.x, s0);         s1 = fmaf(w11, a11.y, s1);
        float t0 = w00 * b00.x;            float t1 = w00 * b00.y;
        t0 = fmaf(w10, b10.x, t0);         t1 = fmaf(w10, b10.y, t1);
        t0 = fmaf(w01, b01.x, t0);         t1 = fmaf(w01, b01.y, t1);
        t0 = fmaf(w11, b11.x, t0);         t1 = fmaf(w11, b11.y, t1);

        c0 = wz0 * s0 + wz1 * t0;
        c1 = wz0 * s1 + wz1 * t1;
    } else {
        // ---- hashed: 4 quad loads (+4B extras for ix%4==3 lanes) ----
        const int hl = lvl - N_CELL;
        const unsigned m0 = (iy * PRIME_Y)           ^ (iz * PRIME_Z);
        const unsigned m1 = (iy * PRIME_Y)           ^ (iz * PRIME_Z + PRIME_Z);
        const unsigned m2 = (iy * PRIME_Y + PRIME_Y) ^ (iz * PRIME_Z);
        const unsigned m3 = (iy * PRIME_Y + PRIME_Y) ^ (iz * PRIME_Z + PRIME_Z);
        const unsigned h0 = (ix ^ m0) & NGP_MASK;
        const unsigned h1 = (ix ^ m1) & NGP_MASK;
        const unsigned h2 = (ix ^ m2) & NGP_MASK;
        const unsigned h3 = (ix ^ m3) & NGP_MASK;

        const uint4* __restrict__ ht = g_ht + hl * (NGP_T / 4);
        const uint4 q0 = __ldg(ht + (h0 >> 2));
        const uint4 q1 = __ldg(ht + (h1 >> 2));
        const uint4 q2 = __ldg(ht + (h2 >> 2));
        const uint4 q3 = __ldg(ht + (h3 >> 2));

        const unsigned jx = ix + 1u;
        const bool extra = (ix & 3u) == 3u;
        float2 e4, e5, e6, e7;
        if (extra) {
            const unsigned* __restrict__ ht32 =
                reinterpret_cast<const unsigned*>(g_ht) + hl * NGP_T;
            const unsigned v4 = __ldg(ht32 + ((jx ^ m0) & NGP_MASK));
            const unsigned v5 = __ldg(ht32 + ((jx ^ m1) & NGP_MASK));
            const unsigned v6 = __ldg(ht32 + ((jx ^ m2) & NGP_MASK));
            const unsigned v7 = __ldg(ht32 + ((jx ^ m3) & NGP_MASK));
            e4 = h2f(v4); e5 = h2f(v5); e6 = h2f(v6); e7 = h2f(v7);
        } else {
            e4 = hsel(q0, (jx ^ m0) & 3u);
            e5 = hsel(q1, (jx ^ m1) & 3u);
            e6 = hsel(q2, (jx ^ m2) & 3u);
            e7 = hsel(q3, (jx ^ m3) & 3u);
        }
        const float2 e0 = hsel(q0, h0 & 3u);
        const float2 e1 = hsel(q1, h1 & 3u);
        const float2 e2 = hsel(q2, h2 & 3u);
        const float2 e3 = hsel(q3, h3 & 3u);

        const float w0 = wx0 * wy0 * wz0;
        const float w1 = wx0 * wy0 * wz1;
        const float w2 = wx0 * wy1 * wz0;
        const float w3 = wx0 * wy1 * wz1;
        const float w4 = wx1 * wy0 * wz0;
        const float w5 = wx1 * wy0 * wz1;
        const float w6 = wx1 * wy1 * wz0;
        const float w7 = wx1 * wy1 * wz1;

        c0 = w0 * e0.x;  c1 = w0 * e0.y;
        c0 = fmaf(w1, e1.x, c0);  c1 = fmaf(w1, e1.y, c1);
        c0 = fmaf(w2, e2.x, c0);  c1 = fmaf(w2, e2.y, c1);
        c0 = fmaf(w3, e3.x, c0);  c1 = fmaf(w3, e3.y, c1);
        c0 = fmaf(w4, e4.x, c0);  c1 = fmaf(w4, e4.y, c1);
        c0 = fmaf(w5, e5.x, c0);  c1 = fmaf(w5, e5.y, c1);
        c0 = fmaf(w6, e6.x, c0);  c1 = fmaf(w6, e6.y, c1);
        c0 = fmaf(w7, e7.x, c0);  c1 = fmaf(w7, e7.y, c1);
    }

    reinterpret_cast<float2*>(out)[pt * NGP_L + lvl] =
        make_float2(c0 * QSCALE_I, c1 * QSCALE_I);
}

extern "C" void kernel_launch(void* const* d_in, const int* in_sizes, int n_in,
                              void* d_out, int out_size)
{
    const float* xyz    = (const float*)d_in[0];
    const float* tables = (const float*)d_in[1];
    float* out          = (float*)d_out;
    const int npts = in_sizes[0] / 3;

    // Reference resolution chain, replicated exactly in libm double.
    NgpParams p;
    const double B = std::exp((std::log(2048.0) - std::log(16.0)) / 15.0);
    for (int i = 0; i < NGP_L; i++) {
        double res_d = std::floor(16.0 * std::pow(B, (double)i));
        float resf   = (float)res_d;
        p.cell[i] = 1.0f / resf;
        p.res[i]  = (int)res_d;
    }
    int qoff = 0;
    p.ccum[0] = 0;
    for (int i = 0; i < N_CELL; i++) {
        p.qoff[i] = qoff;
        const int r = p.res[i];
        const int n = (r + 1) * (r + 1) * (r + 2);
        qoff += n;
        p.ccum[i + 1] = p.ccum[i] + n;
    }
    // qoff = 2,294,340 <= QCAP for the reference chain.

    // 1) fused precompute
    {
        const int ntot = HCONV_ITEMS + p.ccum[N_CELL];
        ngp_prep_kernel<<<(ntot + 255) / 256, 256>>>(tables, p, ntot);
    }
    // 2) main encode
    {
        const int total = npts * NGP_L;
        InstantNGP_kernel<<<(total + 255) / 256, 256>>>(xyz, out, p, npts);
    }
}